// round 12
// baseline (speedup 1.0000x reference)
#include <cuda_runtime.h>
#include <cuda_fp16.h>
#include <cstdint>

#define Bb 8
#define Tt 4096
#define Cc 1024
#define NELEM (8u*4096u*1024u)
#define NCH 32
#define CHL 128
#define BC  (Bb*Cc)

// scratch partition (units of float):
// [0,0.5N) xk_h | [0.5N,N) xv_h | [N,1.5N) xr_h
// [1.5N,2N) k_h | [2N,2.5N) v_h | [2.5N,3N) r_h | [3N,3.5N) ry_h
__device__ float g_scratch[5ull * NELEM];
__device__ float g_state[6ull * BC * NCH];
__device__ float g_wr[2ull * 1024 * 1024];   // 4 weight mats as half (8MB)

// ===========================================================================
// helpers
// ===========================================================================
__device__ __forceinline__ uint32_t smem_to_u32(const void* p) {
    uint32_t a;
    asm("{ .reg .u64 t; cvta.to.shared.u64 t, %1; cvt.u32.u64 %0, t; }"
        : "=r"(a) : "l"(p));
    return a;
}

__device__ __forceinline__ void mma_f16(float c[4], const uint32_t a[4], const uint32_t b[2]) {
    asm volatile(
        "mma.sync.aligned.m16n8k16.row.col.f32.f16.f16.f32 "
        "{%0,%1,%2,%3}, {%4,%5,%6,%7}, {%8,%9}, {%0,%1,%2,%3};\n"
        : "+f"(c[0]), "+f"(c[1]), "+f"(c[2]), "+f"(c[3])
        : "r"(a[0]), "r"(a[1]), "r"(a[2]), "r"(a[3]), "r"(b[0]), "r"(b[1]));
}

__device__ __forceinline__ void ldsm_x4(uint32_t& d0, uint32_t& d1, uint32_t& d2, uint32_t& d3,
                                        uint32_t addr) {
    asm volatile("ldmatrix.sync.aligned.m8n8.x4.shared.b16 {%0,%1,%2,%3}, [%4];"
                 : "=r"(d0), "=r"(d1), "=r"(d2), "=r"(d3) : "r"(addr));
}

__device__ __forceinline__ void cp_async16(uint32_t dst, const void* src) {
    asm volatile("cp.async.cg.shared.global [%0], [%1], 16;" :: "r"(dst), "l"(src));
}
#define CP_COMMIT() asm volatile("cp.async.commit_group;" ::: "memory")
#define CP_WAIT1()  asm volatile("cp.async.wait_group 1;" ::: "memory")

// ===========================================================================
// Fused prep: weight rounding (blocks [MIXB, MIXB+WB)) + time-mix (blocks [0, MIXB))
// ===========================================================================
#define MIXB 32768        // (B*T*C/4)/256
#define WB   1024         // (1024*1024/4)/256

__global__ void prep_kernel(const float4* __restrict__ x4,
                            const float4* __restrict__ tmk4,
                            const float4* __restrict__ tmv4,
                            const float4* __restrict__ tmr4,
                            __half2* __restrict__ xk2,
                            __half2* __restrict__ xv2,
                            __half2* __restrict__ xr2,
                            const float4* __restrict__ w0, const float4* __restrict__ w1,
                            const float4* __restrict__ w2, const float4* __restrict__ w3,
                            __half2* __restrict__ o0, __half2* __restrict__ o1,
                            __half2* __restrict__ o2, __half2* __restrict__ o3) {
    if (blockIdx.x < MIXB) {
        int i = blockIdx.x * blockDim.x + threadIdx.x;
        int c4 = i & (Cc/4 - 1);
        int bt = i >> 8;
        int t  = bt & (Tt - 1);
        float4 xc = x4[i];
        float4 xp = make_float4(0.f, 0.f, 0.f, 0.f);
        if (t != 0) xp = x4[i - Cc/4];
        float4 mk = tmk4[c4], mv = tmv4[c4], mr = tmr4[c4];
        xk2[i*2]   = __floats2half2_rn(xc.x*mk.x + xp.x*(1.f-mk.x), xc.y*mk.y + xp.y*(1.f-mk.y));
        xk2[i*2+1] = __floats2half2_rn(xc.z*mk.z + xp.z*(1.f-mk.z), xc.w*mk.w + xp.w*(1.f-mk.w));
        xv2[i*2]   = __floats2half2_rn(xc.x*mv.x + xp.x*(1.f-mv.x), xc.y*mv.y + xp.y*(1.f-mv.y));
        xv2[i*2+1] = __floats2half2_rn(xc.z*mv.z + xp.z*(1.f-mv.z), xc.w*mv.w + xp.w*(1.f-mv.w));
        xr2[i*2]   = __floats2half2_rn(xc.x*mr.x + xp.x*(1.f-mr.x), xc.y*mr.y + xp.y*(1.f-mr.y));
        xr2[i*2+1] = __floats2half2_rn(xc.z*mr.z + xp.z*(1.f-mr.z), xc.w*mr.w + xp.w*(1.f-mr.w));
    } else {
        int i = (blockIdx.x - MIXB) * blockDim.x + threadIdx.x;
        float4 a = w0[i], b = w1[i], c = w2[i], d = w3[i];
        o0[i*2]   = __floats2half2_rn(a.x, a.y);
        o0[i*2+1] = __floats2half2_rn(a.z, a.w);
        o1[i*2]   = __floats2half2_rn(b.x, b.y);
        o1[i*2+1] = __floats2half2_rn(b.z, b.w);
        o2[i*2]   = __floats2half2_rn(c.x, c.y);
        o2[i*2+1] = __floats2half2_rn(c.z, c.w);
        o3[i*2]   = __floats2half2_rn(d.x, d.y);
        o3[i*2+1] = __floats2half2_rn(d.z, d.w);
    }
}

// ===========================================================================
// FP16 GEMM core: CTA 128x128, 256 threads / 8 warps (warp tile 64x32),
// stage K=64 halves, 3-stage cp.async, ldmatrix.x4, 144B pitch.
// ===========================================================================
#define BM 128
#define BN 128
#define BKH 64
#define PH  72
#define NST 3
#define TILE_BYTES (BM * PH * 2)            // 18432
#define STAGE_BYTES (2 * TILE_BYTES)        // 36864
#define GEMM_SMEM (NST * STAGE_BYTES)       // 110592 -> 2 CTAs/SM
#define NSTEP (Cc / BKH)                    // 16

__device__ __forceinline__ void gemm_issue_stage(
    const __half* __restrict__ Ablk, const __half* __restrict__ Wblk,
    uint32_t sbase, int s, int tid) {
    int buf = s % NST;
    uint32_t sA = sbase + (uint32_t)buf * STAGE_BYTES;
    uint32_t sB = sA + TILE_BYTES;
    int k0 = s * BKH;
    #pragma unroll
    for (int i = 0; i < 4; i++) {
        int idx = i * 256 + tid;
        int row = idx >> 3;
        int ch  = idx & 7;
        cp_async16(sA + (uint32_t)(row * 144 + ch * 16),
                   Ablk + (size_t)row * Cc + k0 + ch * 8);
        cp_async16(sB + (uint32_t)(row * 144 + ch * 16),
                   Wblk + (size_t)row * Cc + k0 + ch * 8);
    }
    CP_COMMIT();
}

__device__ __forceinline__ void load_frags(
    uint32_t aT, uint32_t bT, int ks, int wM, int wN, int lane,
    uint32_t af[4][4], uint32_t bf[4][2]) {
    const int rowSel = lane & 15;
    const int kOff   = ks * 16 + ((lane & 16) >> 1);
    #pragma unroll
    for (int mt = 0; mt < 4; mt++) {
        int row = wM * 64 + mt * 16 + rowSel;
        ldsm_x4(af[mt][0], af[mt][1], af[mt][2], af[mt][3],
                aT + (uint32_t)(row * PH + kOff) * 2);
    }
    #pragma unroll
    for (int j = 0; j < 2; j++) {
        int n0 = wN * 32 + j * 16 + rowSel;
        ldsm_x4(bf[2*j][0], bf[2*j+1][0], bf[2*j][1], bf[2*j+1][1],
                bT + (uint32_t)(n0 * PH + kOff) * 2);
    }
}

// GEMM body shared by both kernels.
// EPI: 0 identity, 1 sigmoid.  HOUT: 1 fp16 out, 0 fp32 out.
template <int EPI, int HOUT>
__device__ __forceinline__ void gemm_body(
    const __half* __restrict__ A, const __half* __restrict__ W,
    void* __restrict__ OutV, uint32_t sbase, int bm, int bn) {
    const int tid  = threadIdx.x;
    const int warp = tid >> 5, lane = tid & 31;
    const int wM = warp >> 2, wN = warp & 3;
    const int grp = lane >> 2, qd = lane & 3;

    const __half* Ablk = A + (size_t)bm * BM * Cc;
    const __half* Wblk = W + (size_t)bn * BN * Cc;

    float acc[4][4][4];
    #pragma unroll
    for (int mt = 0; mt < 4; mt++)
        #pragma unroll
        for (int nt = 0; nt < 4; nt++)
            #pragma unroll
            for (int j = 0; j < 4; j++) acc[mt][nt][j] = 0.f;

    gemm_issue_stage(Ablk, Wblk, sbase, 0, tid);
    gemm_issue_stage(Ablk, Wblk, sbase, 1, tid);

    uint32_t af[2][4][4], bf[2][4][2];

    CP_WAIT1();
    __syncthreads();
    load_frags(sbase, sbase + TILE_BYTES, 0, wM, wN, lane, af[0], bf[0]);

    for (int s = 0; s < NSTEP; s++) {
        const int buf = s % NST;
        const uint32_t aT = sbase + (uint32_t)buf * STAGE_BYTES;
        const uint32_t bT = aT + TILE_BYTES;

        #pragma unroll
        for (int mt = 0; mt < 4; mt++)
            #pragma unroll
            for (int nt = 0; nt < 4; nt++)
                mma_f16(acc[mt][nt], af[0][mt], bf[0][nt]);

        if (s + 2 < NSTEP) gemm_issue_stage(Ablk, Wblk, sbase, s + 2, tid);
        else CP_COMMIT();

        #pragma unroll
        for (int ks = 1; ks < 4; ks++) {
            const int cur = ks & 1;
            load_frags(aT, bT, ks, wM, wN, lane, af[cur], bf[cur]);
            #pragma unroll
            for (int mt = 0; mt < 4; mt++)
                #pragma unroll
                for (int nt = 0; nt < 4; nt++)
                    mma_f16(acc[mt][nt], af[cur][mt], bf[cur][nt]);
        }

        if (s + 1 < NSTEP) {
            CP_WAIT1();
            __syncthreads();
            const int nbuf = (s + 1) % NST;
            const uint32_t aN = sbase + (uint32_t)nbuf * STAGE_BYTES;
            load_frags(aN, aN + TILE_BYTES, 0, wM, wN, lane, af[0], bf[0]);
        }
    }

    #pragma unroll
    for (int mt = 0; mt < 4; mt++) {
        #pragma unroll
        for (int nt = 0; nt < 4; nt++) {
            int m0 = bm * BM + wM * 64 + mt * 16 + grp;
            int n0 = bn * BN + wN * 32 + nt * 8 + qd * 2;
            float v0 = acc[mt][nt][0], v1 = acc[mt][nt][1];
            float v2 = acc[mt][nt][2], v3 = acc[mt][nt][3];
            if (EPI == 1) {
                v0 = 1.f / (1.f + __expf(-v0));
                v1 = 1.f / (1.f + __expf(-v1));
                v2 = 1.f / (1.f + __expf(-v2));
                v3 = 1.f / (1.f + __expf(-v3));
            }
            if (HOUT) {
                __half* O = (__half*)OutV;
                *(__half2*)&O[(size_t)m0 * Cc + n0]       = __floats2half2_rn(v0, v1);
                *(__half2*)&O[(size_t)(m0 + 8) * Cc + n0] = __floats2half2_rn(v2, v3);
            } else {
                float* O = (float*)OutV;
                *(float2*)&O[(size_t)m0 * Cc + n0]       = make_float2(v0, v1);
                *(float2*)&O[(size_t)(m0 + 8) * Cc + n0] = make_float2(v2, v3);
            }
        }
    }
}

// Fused projection GEMM: z = 0 (k), 1 (v), 2 (r, sigmoid). All fp16 out.
__global__ __launch_bounds__(256, 2)
void gemm_proj(const __half* __restrict__ A0, const __half* __restrict__ W0, __half* O0,
               const __half* __restrict__ A1, const __half* __restrict__ W1, __half* O1,
               const __half* __restrict__ A2, const __half* __restrict__ W2, __half* O2) {
    extern __shared__ char smc[];
    const uint32_t sbase = smem_to_u32(smc);
    const int bn = blockIdx.x, bm = blockIdx.y, z = blockIdx.z;
    if (z == 0)      gemm_body<0,1>(A0, W0, O0, sbase, bm, bn);
    else if (z == 1) gemm_body<0,1>(A1, W1, O1, sbase, bm, bn);
    else             gemm_body<1,1>(A2, W2, O2, sbase, bm, bn);
}

// Final GEMM: fp32 out.
__global__ __launch_bounds__(256, 2)
void gemm_out(const __half* __restrict__ A, const __half* __restrict__ W, float* O) {
    extern __shared__ char smc[];
    const uint32_t sbase = smem_to_u32(smc);
    gemm_body<0,0>(A, W, O, sbase, blockIdx.y, blockIdx.x);
}

// ===========================================================================
// WKV chunk-parallel scan (fp16 K/V/R, fp32 math)
// ===========================================================================
__global__ void wkv_phase1(const __half* __restrict__ K, const __half* __restrict__ V,
                           const float* __restrict__ time_decay,
                           float* __restrict__ st_aa, float* __restrict__ st_bb,
                           float* __restrict__ st_pp) {
    int idx = blockIdx.x * blockDim.x + threadIdx.x;
    int bc = idx & (BC - 1);
    int ch = idx >> 13;
    int c  = bc & (Cc - 1);
    int b  = bc >> 10;
    float w = -__expf(time_decay[c]);

    float aa = 0.f, bb = 0.f, pp = -1e30f;
    size_t off = ((size_t)b * Tt + (size_t)ch * CHL) * Cc + c;
    for (int t = 0; t < CHL; t++) {
        float kt = __half2float(K[off]);
        float vt = __half2float(V[off]);
        float ww2 = w + pp;
        float p2  = fmaxf(ww2, kt);
        float e1b = __expf(ww2 - p2);
        float e2b = __expf(kt - p2);
        aa = aa * e1b + vt * e2b;
        bb = bb * e1b + e2b;
        pp = p2;
        off += Cc;
    }
    st_aa[idx] = aa; st_bb[idx] = bb; st_pp[idx] = pp;
}

__global__ void wkv_phase2(const float* __restrict__ time_decay,
                           const float* __restrict__ st_aa, const float* __restrict__ st_bb,
                           const float* __restrict__ st_pp,
                           float* __restrict__ in_aa, float* __restrict__ in_bb,
                           float* __restrict__ in_pp) {
    int bc = blockIdx.x * blockDim.x + threadIdx.x;
    int c  = bc & (Cc - 1);
    float w  = -__expf(time_decay[c]);
    float wL = w * (float)CHL;

    float aa = 0.f, bb = 0.f, pp = -1e30f;
    for (int ch = 0; ch < NCH; ch++) {
        int i = ch * BC + bc;
        in_aa[i] = aa; in_bb[i] = bb; in_pp[i] = pp;
        float la = st_aa[i], lb = st_bb[i], lp = st_pp[i];
        float pn   = fmaxf(pp + wL, lp);
        float e_in = __expf(pp + wL - pn);
        float e_lc = __expf(lp - pn);
        aa = aa * e_in + la * e_lc;
        bb = bb * e_in + lb * e_lc;
        pp = pn;
    }
}

__global__ void wkv_phase3(const __half* __restrict__ K, const __half* __restrict__ V,
                           const __half* __restrict__ R, __half* __restrict__ RY,
                           const float* __restrict__ time_decay,
                           const float* __restrict__ time_first,
                           const float* __restrict__ in_aa, const float* __restrict__ in_bb,
                           const float* __restrict__ in_pp) {
    int idx = blockIdx.x * blockDim.x + threadIdx.x;
    int bc = idx & (BC - 1);
    int ch = idx >> 13;
    int c  = bc & (Cc - 1);
    int b  = bc >> 10;
    float w = -__expf(time_decay[c]);
    float u = time_first[c];

    float aa = in_aa[idx], bb = in_bb[idx], pp = in_pp[idx];
    size_t off = ((size_t)b * Tt + (size_t)ch * CHL) * Cc + c;
    for (int t = 0; t < CHL; t++) {
        float kt = __half2float(K[off]);
        float vt = __half2float(V[off]);

        float ww = u + pp;
        float p  = fmaxf(ww, kt);
        float e1 = __expf(ww - p);
        float e2 = __expf(kt - p);
        float y  = (aa * e1 + vt * e2) / (bb * e1 + e2 + 1e-6f);
        RY[off] = __float2half_rn(y * __half2float(R[off]));

        float ww2 = w + pp;
        float p2  = fmaxf(ww2, kt);
        float e1b = __expf(ww2 - p2);
        float e2b = __expf(kt - p2);
        aa = aa * e1b + vt * e2b;
        bb = bb * e1b + e2b;
        pp = p2;
        off += Cc;
    }
}

// ===========================================================================
// Launch
// ===========================================================================
extern "C" void kernel_launch(void* const* d_in, const int* in_sizes, int n_in,
                              void* d_out, int out_size) {
    const float* x          = (const float*)d_in[0];
    const float* time_decay = (const float*)d_in[1];
    const float* time_first = (const float*)d_in[2];
    const float* tmk        = (const float*)d_in[3];
    const float* tmv        = (const float*)d_in[4];
    const float* tmr        = (const float*)d_in[5];
    const float* Wk         = (const float*)d_in[6];
    const float* Wv         = (const float*)d_in[7];
    const float* Wr         = (const float*)d_in[8];
    const float* Wo         = (const float*)d_in[9];
    float* out = (float*)d_out;

    float* scratch = nullptr;
    cudaGetSymbolAddress((void**)&scratch, g_scratch);
    __half* h_xk = (__half*)(scratch);
    __half* h_xv = (__half*)(scratch + NELEM / 2);
    __half* h_xr = (__half*)(scratch + NELEM);
    __half* h_k  = (__half*)(scratch + 3ull * NELEM / 2);
    __half* h_v  = (__half*)(scratch + 4ull * NELEM / 2);
    __half* h_r  = (__half*)(scratch + 5ull * NELEM / 2);
    __half* h_ry = (__half*)(scratch + 6ull * NELEM / 2);

    float* state = nullptr;
    cudaGetSymbolAddress((void**)&state, g_state);
    float* st_aa = state + 0ull * BC * NCH;
    float* st_bb = state + 1ull * BC * NCH;
    float* st_pp = state + 2ull * BC * NCH;
    float* in_aa = state + 3ull * BC * NCH;
    float* in_bb = state + 4ull * BC * NCH;
    float* in_pp = state + 5ull * BC * NCH;

    float* wr = nullptr;
    cudaGetSymbolAddress((void**)&wr, g_wr);
    __half* hWk = (__half*)(wr);
    __half* hWv = (__half*)(wr) + 1ull * 1024 * 1024;
    __half* hWr = (__half*)(wr) + 2ull * 1024 * 1024;
    __half* hWo = (__half*)(wr) + 3ull * 1024 * 1024;

    cudaFuncSetAttribute(gemm_proj, cudaFuncAttributeMaxDynamicSharedMemorySize, GEMM_SMEM);
    cudaFuncSetAttribute(gemm_out,  cudaFuncAttributeMaxDynamicSharedMemorySize, GEMM_SMEM);

    // 1. fused prep: mix -> fp16 + weights -> fp16
    prep_kernel<<<MIXB + WB, 256>>>(
        (const float4*)x, (const float4*)tmk, (const float4*)tmv, (const float4*)tmr,
        (__half2*)h_xk, (__half2*)h_xv, (__half2*)h_xr,
        (const float4*)Wk, (const float4*)Wv, (const float4*)Wr, (const float4*)Wo,
        (__half2*)hWk, (__half2*)hWv, (__half2*)hWr, (__half2*)hWo);

    // 2. fused projections: k, v, r(sigmoid) in one launch
    {
        dim3 grid(Cc / BN, (Bb * Tt) / BM, 3);   // (8, 256, 3)
        gemm_proj<<<grid, 256, GEMM_SMEM>>>(h_xk, hWk, h_k,
                                            h_xv, hWv, h_v,
                                            h_xr, hWr, h_r);
    }

    // 3. chunk-parallel WKV; ry (fp16) -> h_ry
    wkv_phase1<<<(BC * NCH) / 256, 256>>>(h_k, h_v, time_decay, st_aa, st_bb, st_pp);
    wkv_phase2<<<BC / 256, 256>>>(time_decay, st_aa, st_bb, st_pp, in_aa, in_bb, in_pp);
    wkv_phase3<<<(BC * NCH) / 256, 256>>>(h_k, h_v, h_r, h_ry, time_decay, time_first,
                                          in_aa, in_bb, in_pp);

    // 4. out = ry @ Wo^T (fp32 output)
    {
        dim3 grid(Cc / BN, (Bb * Tt) / BM);      // (8, 256)
        gemm_out<<<grid, 256, GEMM_SMEM>>>(h_ry, hWo, out);
    }
}

// round 13
// speedup vs baseline: 1.0463x; 1.0463x over previous
#include <cuda_runtime.h>
#include <cuda_fp16.h>
#include <cstdint>

#define Bb 8
#define Tt 4096
#define Cc 1024
#define NELEM (8u*4096u*1024u)
#define NCH 32
#define CHL 128
#define BC  (Bb*Cc)

// scratch partition (units of float):
// [0,0.5N) xk_h | [0.5N,N) xv_h | [N,1.5N) xr_h
// [1.5N,2N) k_h | [2N,2.5N) v_h | [2.5N,3N) r_h | [3N,3.5N) ry_h
__device__ float g_scratch[5ull * NELEM];
__device__ float g_state[6ull * BC * NCH];
__device__ float g_wr[2ull * 1024 * 1024];   // 4 weight mats as half (8MB)

// ===========================================================================
// helpers
// ===========================================================================
__device__ __forceinline__ uint32_t smem_to_u32(const void* p) {
    uint32_t a;
    asm("{ .reg .u64 t; cvta.to.shared.u64 t, %1; cvt.u32.u64 %0, t; }"
        : "=r"(a) : "l"(p));
    return a;
}

__device__ __forceinline__ void mma_f16(float c[4], const uint32_t a[4], const uint32_t b[2]) {
    asm volatile(
        "mma.sync.aligned.m16n8k16.row.col.f32.f16.f16.f32 "
        "{%0,%1,%2,%3}, {%4,%5,%6,%7}, {%8,%9}, {%0,%1,%2,%3};\n"
        : "+f"(c[0]), "+f"(c[1]), "+f"(c[2]), "+f"(c[3])
        : "r"(a[0]), "r"(a[1]), "r"(a[2]), "r"(a[3]), "r"(b[0]), "r"(b[1]));
}

__device__ __forceinline__ void ldsm_x4(uint32_t& d0, uint32_t& d1, uint32_t& d2, uint32_t& d3,
                                        uint32_t addr) {
    asm volatile("ldmatrix.sync.aligned.m8n8.x4.shared.b16 {%0,%1,%2,%3}, [%4];"
                 : "=r"(d0), "=r"(d1), "=r"(d2), "=r"(d3) : "r"(addr));
}

__device__ __forceinline__ void cp_async16(uint32_t dst, const void* src) {
    asm volatile("cp.async.cg.shared.global [%0], [%1], 16;" :: "r"(dst), "l"(src));
}
#define CP_COMMIT() asm volatile("cp.async.commit_group;" ::: "memory")
#define CP_WAIT1()  asm volatile("cp.async.wait_group 1;" ::: "memory")

// ===========================================================================
// round all 4 weight matrices to fp16 (single launch)
// ===========================================================================
__global__ void round_w_kernel(const float4* __restrict__ w0, const float4* __restrict__ w1,
                               const float4* __restrict__ w2, const float4* __restrict__ w3,
                               __half2* __restrict__ o0, __half2* __restrict__ o1,
                               __half2* __restrict__ o2, __half2* __restrict__ o3) {
    int i = blockIdx.x * blockDim.x + threadIdx.x;
    float4 a = w0[i], b = w1[i], c = w2[i], d = w3[i];
    o0[i*2]   = __floats2half2_rn(a.x, a.y);
    o0[i*2+1] = __floats2half2_rn(a.z, a.w);
    o1[i*2]   = __floats2half2_rn(b.x, b.y);
    o1[i*2+1] = __floats2half2_rn(b.z, b.w);
    o2[i*2]   = __floats2half2_rn(c.x, c.y);
    o2[i*2+1] = __floats2half2_rn(c.z, c.w);
    o3[i*2]   = __floats2half2_rn(d.x, d.y);
    o3[i*2+1] = __floats2half2_rn(d.z, d.w);
}

// ===========================================================================
// Mix kernel: fp16 outputs
// ===========================================================================
__global__ void mix_kernel(const float4* __restrict__ x4,
                           const float4* __restrict__ tmk4,
                           const float4* __restrict__ tmv4,
                           const float4* __restrict__ tmr4,
                           __half2* __restrict__ xk2,
                           __half2* __restrict__ xv2,
                           __half2* __restrict__ xr2) {
    int i = blockIdx.x * blockDim.x + threadIdx.x;
    int c4 = i & (Cc/4 - 1);
    int bt = i >> 8;
    int t  = bt & (Tt - 1);
    float4 xc = x4[i];
    float4 xp = make_float4(0.f, 0.f, 0.f, 0.f);
    if (t != 0) xp = x4[i - Cc/4];
    float4 mk = tmk4[c4], mv = tmv4[c4], mr = tmr4[c4];
    xk2[i*2]   = __floats2half2_rn(xc.x*mk.x + xp.x*(1.f-mk.x), xc.y*mk.y + xp.y*(1.f-mk.y));
    xk2[i*2+1] = __floats2half2_rn(xc.z*mk.z + xp.z*(1.f-mk.z), xc.w*mk.w + xp.w*(1.f-mk.w));
    xv2[i*2]   = __floats2half2_rn(xc.x*mv.x + xp.x*(1.f-mv.x), xc.y*mv.y + xp.y*(1.f-mv.y));
    xv2[i*2+1] = __floats2half2_rn(xc.z*mv.z + xp.z*(1.f-mv.z), xc.w*mv.w + xp.w*(1.f-mv.w));
    xr2[i*2]   = __floats2half2_rn(xc.x*mr.x + xp.x*(1.f-mr.x), xc.y*mr.y + xp.y*(1.f-mr.y));
    xr2[i*2+1] = __floats2half2_rn(xc.z*mr.z + xp.z*(1.f-mr.z), xc.w*mr.w + xp.w*(1.f-mr.w));
}

// ===========================================================================
// FP16 GEMM: CTA 128x128, 256 threads / 8 warps (warp tile 64x32),
// stage K=64 halves, 3-stage cp.async, ldmatrix.x4, 144B pitch.
// EPI: 0 identity, 1 sigmoid.  HOUT: 1 fp16 out, 0 fp32 out.
// ===========================================================================
#define BM 128
#define BN 128
#define BKH 64
#define PH  72
#define NST 3
#define TILE_BYTES (BM * PH * 2)            // 18432
#define STAGE_BYTES (2 * TILE_BYTES)        // 36864
#define GEMM_SMEM (NST * STAGE_BYTES)       // 110592 -> 2 CTAs/SM
#define NSTEP (Cc / BKH)                    // 16

__device__ __forceinline__ void gemm_issue_stage(
    const __half* __restrict__ Ablk, const __half* __restrict__ Wblk,
    uint32_t sbase, int s, int tid) {
    int buf = s % NST;
    uint32_t sA = sbase + (uint32_t)buf * STAGE_BYTES;
    uint32_t sB = sA + TILE_BYTES;
    int k0 = s * BKH;
    #pragma unroll
    for (int i = 0; i < 4; i++) {
        int idx = i * 256 + tid;
        int row = idx >> 3;
        int ch  = idx & 7;
        cp_async16(sA + (uint32_t)(row * 144 + ch * 16),
                   Ablk + (size_t)row * Cc + k0 + ch * 8);
        cp_async16(sB + (uint32_t)(row * 144 + ch * 16),
                   Wblk + (size_t)row * Cc + k0 + ch * 8);
    }
    CP_COMMIT();
}

__device__ __forceinline__ void load_frags(
    uint32_t aT, uint32_t bT, int ks, int wM, int wN, int lane,
    uint32_t af[4][4], uint32_t bf[4][2]) {
    const int rowSel = lane & 15;
    const int kOff   = ks * 16 + ((lane & 16) >> 1);
    #pragma unroll
    for (int mt = 0; mt < 4; mt++) {
        int row = wM * 64 + mt * 16 + rowSel;
        ldsm_x4(af[mt][0], af[mt][1], af[mt][2], af[mt][3],
                aT + (uint32_t)(row * PH + kOff) * 2);
    }
    #pragma unroll
    for (int j = 0; j < 2; j++) {
        int n0 = wN * 32 + j * 16 + rowSel;
        ldsm_x4(bf[2*j][0], bf[2*j+1][0], bf[2*j][1], bf[2*j+1][1],
                bT + (uint32_t)(n0 * PH + kOff) * 2);
    }
}

template <int EPI, int HOUT>
__global__ __launch_bounds__(256, 2)
void gemm_f16(const __half* __restrict__ A, const __half* __restrict__ W,
              void* __restrict__ OutV) {
    extern __shared__ char smc[];
    const uint32_t sbase = smem_to_u32(smc);
    const int tid  = threadIdx.x;
    const int warp = tid >> 5, lane = tid & 31;
    const int wM = warp >> 2, wN = warp & 3;
    const int grp = lane >> 2, qd = lane & 3;
    const int bn = blockIdx.x, bm = blockIdx.y;

    const __half* Ablk = A + (size_t)bm * BM * Cc;
    const __half* Wblk = W + (size_t)bn * BN * Cc;

    float acc[4][4][4];
    #pragma unroll
    for (int mt = 0; mt < 4; mt++)
        #pragma unroll
        for (int nt = 0; nt < 4; nt++)
            #pragma unroll
            for (int j = 0; j < 4; j++) acc[mt][nt][j] = 0.f;

    gemm_issue_stage(Ablk, Wblk, sbase, 0, tid);
    gemm_issue_stage(Ablk, Wblk, sbase, 1, tid);

    uint32_t af[2][4][4], bf[2][4][2];

    CP_WAIT1();
    __syncthreads();
    load_frags(sbase, sbase + TILE_BYTES, 0, wM, wN, lane, af[0], bf[0]);

    for (int s = 0; s < NSTEP; s++) {
        const int buf = s % NST;
        const uint32_t aT = sbase + (uint32_t)buf * STAGE_BYTES;
        const uint32_t bT = aT + TILE_BYTES;

        #pragma unroll
        for (int mt = 0; mt < 4; mt++)
            #pragma unroll
            for (int nt = 0; nt < 4; nt++)
                mma_f16(acc[mt][nt], af[0][mt], bf[0][nt]);

        if (s + 2 < NSTEP) gemm_issue_stage(Ablk, Wblk, sbase, s + 2, tid);
        else CP_COMMIT();

        #pragma unroll
        for (int ks = 1; ks < 4; ks++) {
            const int cur = ks & 1;
            load_frags(aT, bT, ks, wM, wN, lane, af[cur], bf[cur]);
            #pragma unroll
            for (int mt = 0; mt < 4; mt++)
                #pragma unroll
                for (int nt = 0; nt < 4; nt++)
                    mma_f16(acc[mt][nt], af[cur][mt], bf[cur][nt]);
        }

        if (s + 1 < NSTEP) {
            CP_WAIT1();
            __syncthreads();
            const int nbuf = (s + 1) % NST;
            const uint32_t aN = sbase + (uint32_t)nbuf * STAGE_BYTES;
            load_frags(aN, aN + TILE_BYTES, 0, wM, wN, lane, af[0], bf[0]);
        }
    }

    #pragma unroll
    for (int mt = 0; mt < 4; mt++) {
        #pragma unroll
        for (int nt = 0; nt < 4; nt++) {
            int m0 = bm * BM + wM * 64 + mt * 16 + grp;
            int n0 = bn * BN + wN * 32 + nt * 8 + qd * 2;
            float v0 = acc[mt][nt][0], v1 = acc[mt][nt][1];
            float v2 = acc[mt][nt][2], v3 = acc[mt][nt][3];
            if (EPI == 1) {
                v0 = 1.f / (1.f + __expf(-v0));
                v1 = 1.f / (1.f + __expf(-v1));
                v2 = 1.f / (1.f + __expf(-v2));
                v3 = 1.f / (1.f + __expf(-v3));
            }
            if (HOUT) {
                __half* O = (__half*)OutV;
                *(__half2*)&O[(size_t)m0 * Cc + n0]       = __floats2half2_rn(v0, v1);
                *(__half2*)&O[(size_t)(m0 + 8) * Cc + n0] = __floats2half2_rn(v2, v3);
            } else {
                float* O = (float*)OutV;
                *(float2*)&O[(size_t)m0 * Cc + n0]       = make_float2(v0, v1);
                *(float2*)&O[(size_t)(m0 + 8) * Cc + n0] = make_float2(v2, v3);
            }
        }
    }
}

// ===========================================================================
// WKV chunk-parallel scan (fp16 K/V/R, fp32 math)
// ===========================================================================
__global__ void wkv_phase1(const __half* __restrict__ K, const __half* __restrict__ V,
                           const float* __restrict__ time_decay,
                           float* __restrict__ st_aa, float* __restrict__ st_bb,
                           float* __restrict__ st_pp) {
    int idx = blockIdx.x * blockDim.x + threadIdx.x;
    int bc = idx & (BC - 1);
    int ch = idx >> 13;
    int c  = bc & (Cc - 1);
    int b  = bc >> 10;
    float w = -__expf(time_decay[c]);

    float aa = 0.f, bb = 0.f, pp = -1e30f;
    size_t off = ((size_t)b * Tt + (size_t)ch * CHL) * Cc + c;
    for (int t = 0; t < CHL; t++) {
        float kt = __half2float(K[off]);
        float vt = __half2float(V[off]);
        float ww2 = w + pp;
        float p2  = fmaxf(ww2, kt);
        float e1b = __expf(ww2 - p2);
        float e2b = __expf(kt - p2);
        aa = aa * e1b + vt * e2b;
        bb = bb * e1b + e2b;
        pp = p2;
        off += Cc;
    }
    st_aa[idx] = aa; st_bb[idx] = bb; st_pp[idx] = pp;
}

__global__ void wkv_phase2(const float* __restrict__ time_decay,
                           const float* __restrict__ st_aa, const float* __restrict__ st_bb,
                           const float* __restrict__ st_pp,
                           float* __restrict__ in_aa, float* __restrict__ in_bb,
                           float* __restrict__ in_pp) {
    int bc = blockIdx.x * blockDim.x + threadIdx.x;
    int c  = bc & (Cc - 1);
    float w  = -__expf(time_decay[c]);
    float wL = w * (float)CHL;

    float aa = 0.f, bb = 0.f, pp = -1e30f;
    for (int ch = 0; ch < NCH; ch++) {
        int i = ch * BC + bc;
        in_aa[i] = aa; in_bb[i] = bb; in_pp[i] = pp;
        float la = st_aa[i], lb = st_bb[i], lp = st_pp[i];
        float pn   = fmaxf(pp + wL, lp);
        float e_in = __expf(pp + wL - pn);
        float e_lc = __expf(lp - pn);
        aa = aa * e_in + la * e_lc;
        bb = bb * e_in + lb * e_lc;
        pp = pn;
    }
}

__global__ void wkv_phase3(const __half* __restrict__ K, const __half* __restrict__ V,
                           const __half* __restrict__ R, __half* __restrict__ RY,
                           const float* __restrict__ time_decay,
                           const float* __restrict__ time_first,
                           const float* __restrict__ in_aa, const float* __restrict__ in_bb,
                           const float* __restrict__ in_pp) {
    int idx = blockIdx.x * blockDim.x + threadIdx.x;
    int bc = idx & (BC - 1);
    int ch = idx >> 13;
    int c  = bc & (Cc - 1);
    int b  = bc >> 10;
    float w = -__expf(time_decay[c]);
    float u = time_first[c];

    float aa = in_aa[idx], bb = in_bb[idx], pp = in_pp[idx];
    size_t off = ((size_t)b * Tt + (size_t)ch * CHL) * Cc + c;
    for (int t = 0; t < CHL; t++) {
        float kt = __half2float(K[off]);
        float vt = __half2float(V[off]);

        float ww = u + pp;
        float p  = fmaxf(ww, kt);
        float e1 = __expf(ww - p);
        float e2 = __expf(kt - p);
        float y  = (aa * e1 + vt * e2) / (bb * e1 + e2 + 1e-6f);
        RY[off] = __float2half_rn(y * __half2float(R[off]));

        float ww2 = w + pp;
        float p2  = fmaxf(ww2, kt);
        float e1b = __expf(ww2 - p2);
        float e2b = __expf(kt - p2);
        aa = aa * e1b + vt * e2b;
        bb = bb * e1b + e2b;
        pp = p2;
        off += Cc;
    }
}

// ===========================================================================
// Launch: fork-join — gemm_r runs on a side stream concurrent with
// wkv_phase1 + wkv_phase2 (independent work), joined before phase3.
// ===========================================================================
extern "C" void kernel_launch(void* const* d_in, const int* in_sizes, int n_in,
                              void* d_out, int out_size) {
    const float* x          = (const float*)d_in[0];
    const float* time_decay = (const float*)d_in[1];
    const float* time_first = (const float*)d_in[2];
    const float* tmk        = (const float*)d_in[3];
    const float* tmv        = (const float*)d_in[4];
    const float* tmr        = (const float*)d_in[5];
    const float* Wk         = (const float*)d_in[6];
    const float* Wv         = (const float*)d_in[7];
    const float* Wr         = (const float*)d_in[8];
    const float* Wo         = (const float*)d_in[9];
    float* out = (float*)d_out;

    float* scratch = nullptr;
    cudaGetSymbolAddress((void**)&scratch, g_scratch);
    __half* h_xk = (__half*)(scratch);
    __half* h_xv = (__half*)(scratch + NELEM / 2);
    __half* h_xr = (__half*)(scratch + NELEM);
    __half* h_k  = (__half*)(scratch + 3ull * NELEM / 2);
    __half* h_v  = (__half*)(scratch + 4ull * NELEM / 2);
    __half* h_r  = (__half*)(scratch + 5ull * NELEM / 2);
    __half* h_ry = (__half*)(scratch + 6ull * NELEM / 2);

    float* state = nullptr;
    cudaGetSymbolAddress((void**)&state, g_state);
    float* st_aa = state + 0ull * BC * NCH;
    float* st_bb = state + 1ull * BC * NCH;
    float* st_pp = state + 2ull * BC * NCH;
    float* in_aa = state + 3ull * BC * NCH;
    float* in_bb = state + 4ull * BC * NCH;
    float* in_pp = state + 5ull * BC * NCH;

    float* wr = nullptr;
    cudaGetSymbolAddress((void**)&wr, g_wr);
    __half* hWk = (__half*)(wr);
    __half* hWv = (__half*)(wr) + 1ull * 1024 * 1024;
    __half* hWr = (__half*)(wr) + 2ull * 1024 * 1024;
    __half* hWo = (__half*)(wr) + 3ull * 1024 * 1024;

    cudaFuncSetAttribute(gemm_f16<0,0>, cudaFuncAttributeMaxDynamicSharedMemorySize, GEMM_SMEM);
    cudaFuncSetAttribute(gemm_f16<0,1>, cudaFuncAttributeMaxDynamicSharedMemorySize, GEMM_SMEM);
    cudaFuncSetAttribute(gemm_f16<1,1>, cudaFuncAttributeMaxDynamicSharedMemorySize, GEMM_SMEM);

    // one-time side stream + events (host-side resources only)
    static cudaStream_t s1 = nullptr;
    static cudaEvent_t evFork = nullptr, evJoin = nullptr;
    if (!s1) {
        cudaStreamCreateWithFlags(&s1, cudaStreamNonBlocking);
        cudaEventCreateWithFlags(&evFork, cudaEventDisableTiming);
        cudaEventCreateWithFlags(&evJoin, cudaEventDisableTiming);
    }

    // 0. weights -> fp16
    {
        int n4 = 1024 * 1024 / 4;
        round_w_kernel<<<n4 / 256, 256>>>(
            (const float4*)Wk, (const float4*)Wv, (const float4*)Wr, (const float4*)Wo,
            (__half2*)hWk, (__half2*)hWv, (__half2*)hWr, (__half2*)hWo);
    }

    // 1. mix -> fp16
    {
        int total4 = Bb * Tt * Cc / 4;
        mix_kernel<<<total4 / 256, 256>>>((const float4*)x,
                                          (const float4*)tmk, (const float4*)tmv,
                                          (const float4*)tmr,
                                          (__half2*)h_xk, (__half2*)h_xv, (__half2*)h_xr);
    }

    dim3 grid(Cc / BN, (Bb * Tt) / BM);   // (8, 256)

    // 2-3. k and v projections (capture stream)
    gemm_f16<0,1><<<grid, 256, GEMM_SMEM>>>(h_xk, hWk, h_k);
    gemm_f16<0,1><<<grid, 256, GEMM_SMEM>>>(h_xv, hWv, h_v);

    // fork: r projection on side stream, concurrent with phase1+phase2
    cudaEventRecord(evFork, 0);
    cudaStreamWaitEvent(s1, evFork, 0);
    gemm_f16<1,1><<<grid, 256, GEMM_SMEM, s1>>>(h_xr, hWr, h_r);
    cudaEventRecord(evJoin, s1);

    // phase1 + phase2 on capture stream (need only k, v)
    wkv_phase1<<<(BC * NCH) / 256, 256>>>(h_k, h_v, time_decay, st_aa, st_bb, st_pp);
    wkv_phase2<<<BC / 256, 256>>>(time_decay, st_aa, st_bb, st_pp, in_aa, in_bb, in_pp);

    // join: phase3 needs r
    cudaStreamWaitEvent(0, evJoin, 0);
    wkv_phase3<<<(BC * NCH) / 256, 256>>>(h_k, h_v, h_r, h_ry, time_decay, time_first,
                                          in_aa, in_bb, in_pp);

    // 4. out = ry @ Wo^T (fp32 output)
    gemm_f16<0,0><<<grid, 256, GEMM_SMEM>>>(h_ry, hWo, out);
}